// round 13
// baseline (speedup 1.0000x reference)
#include <cuda_runtime.h>
#include <cuda_bf16.h>
#include <cuda_fp16.h>
#include <math_constants.h>

#define N_NODES 100000
#define N_EDGES 1600000
#define D_IN  64
#define D_HID 64
#define D_OUT 40

#define SCAN_B 512
#define NB ((N_NODES + SCAN_B - 1) / SCAN_B)   // 196

// ---------------------------------------------------------------------------
// Scratch (device globals — no runtime allocation allowed)
// ---------------------------------------------------------------------------
__device__ int   g_cnt   [N_NODES];            // in-degree (excl. self loop)
__device__ int   g_rowptr[N_NODES];            // exclusive prefix of cnt
__device__ int   g_cursor[N_NODES];            // bucket fill cursor
__device__ int   g_bsum  [NB];                 // per-scan-block sums
__device__ int   g_esrc  [N_EDGES];            // edge sources sorted by col
__device__ float g_dinv  [N_NODES];
// fp16 storage for gather-heavy tensors (accumulation stays fp32)
__device__ __align__(16) __half g_H1h[(size_t)N_NODES * D_HID]; // (x@W1)*dinv[row]
__device__ __align__(16) float  g_B1 [(size_t)N_NODES * D_HID]; // relu(layer-1 out)
__device__ __align__(16) __half g_H2h[(size_t)N_NODES * D_OUT]; // (B1@W2)*dinv[row]

// ---------------------------------------------------------------------------
// (0) zero degree counters
// ---------------------------------------------------------------------------
__global__ void k_zero_cnt() {
    int i = blockIdx.x * blockDim.x + threadIdx.x;
    if (i < N_NODES) g_cnt[i] = 0;
}

// ---------------------------------------------------------------------------
// (1) degree histogram, 8 edges/thread (MLP)
// ---------------------------------------------------------------------------
__global__ void k_hist(const int* __restrict__ ei) {
    int t = blockIdx.x * blockDim.x + threadIdx.x;
    if (t < N_EDGES / 8) {
        int4 c0 = ((const int4*)(ei + N_EDGES))[2 * t];
        int4 c1 = ((const int4*)(ei + N_EDGES))[2 * t + 1];
        atomicAdd(&g_cnt[c0.x], 1);
        atomicAdd(&g_cnt[c0.y], 1);
        atomicAdd(&g_cnt[c0.z], 1);
        atomicAdd(&g_cnt[c0.w], 1);
        atomicAdd(&g_cnt[c1.x], 1);
        atomicAdd(&g_cnt[c1.y], 1);
        atomicAdd(&g_cnt[c1.z], 1);
        atomicAdd(&g_cnt[c1.w], 1);
    }
}

// ---------------------------------------------------------------------------
// (2) per-block sums for the scan + dinv (dinv only needs cnt, not the scan)
// ---------------------------------------------------------------------------
__global__ void k_scan_reduce() {   // <<<NB, SCAN_B>>>
    __shared__ int ssum[SCAN_B / 32];
    int tid = threadIdx.x;
    int i = blockIdx.x * SCAN_B + tid;
    int v = 0;
    if (i < N_NODES) {
        v = g_cnt[i];
        g_dinv[i] = rsqrtf((float)(v + 1));    // +1 self loop
    }
    int r = v;
    #pragma unroll
    for (int o = 16; o > 0; o >>= 1) r += __shfl_down_sync(0xFFFFFFFFu, r, o);
    if ((tid & 31) == 0) ssum[tid >> 5] = r;
    __syncthreads();
    if (tid < SCAN_B / 32) {
        r = ssum[tid];
        #pragma unroll
        for (int o = SCAN_B / 64; o > 0; o >>= 1)
            r += __shfl_down_sync(0xFFFFFFFFu, r, o);
        if (tid == 0) g_bsum[blockIdx.x] = r;
    }
}

// ---------------------------------------------------------------------------
// (3) GEMM1 (PROFILED SLOT): H1h[r] = half( (x[r] @ W1) * dinv[r] )
//     32 rows/block, 8 rows/thread, float4 smem tiling.
// ---------------------------------------------------------------------------
__global__ void k_gemm1(const float* __restrict__ x, const float* __restrict__ W) {
    __shared__ float4 Ws4[16][64];   // Ws4[kk][c] = W[4kk..4kk+3][c]  (16 KB)
    __shared__ float4 Xs4[32][16];   // row-major [32][64] floats      (8 KB)
    int tid = threadIdx.x;
    for (int idx = tid; idx < 16 * 64; idx += 256) {
        int kk = idx >> 6, c = idx & 63, k0 = kk * 4;
        Ws4[kk][c] = make_float4(W[(k0 + 0) * 64 + c], W[(k0 + 1) * 64 + c],
                                 W[(k0 + 2) * 64 + c], W[(k0 + 3) * 64 + c]);
    }
    int row0 = blockIdx.x * 32;
    float* Xf = (float*)Xs4;
    for (int idx = tid; idx < 32 * 64; idx += 256)
        Xf[idx] = x[(size_t)row0 * 64 + idx];
    __syncthreads();

    int tx = tid & 63, ty = tid >> 6;
    float acc[8] = {0, 0, 0, 0, 0, 0, 0, 0};
    #pragma unroll
    for (int kk = 0; kk < 16; kk++) {
        float4 w = Ws4[kk][tx];
        #pragma unroll
        for (int j = 0; j < 8; j++) {
            float4 xv = Xs4[ty * 8 + j][kk];
            acc[j] = fmaf(xv.x, w.x, fmaf(xv.y, w.y,
                     fmaf(xv.z, w.z, fmaf(xv.w, w.w, acc[j]))));
        }
    }
    #pragma unroll
    for (int j = 0; j < 8; j++) {
        int r = row0 + ty * 8 + j;
        g_H1h[(size_t)r * D_HID + tx] = __float2half_rn(acc[j] * g_dinv[r]);
    }
}

// ---------------------------------------------------------------------------
// (4) scan + rowptr/cursor
// ---------------------------------------------------------------------------
__global__ void k_scan_final() {    // <<<NB, SCAN_B>>>
    __shared__ int s[SCAN_B];
    __shared__ int sOff;
    int t = threadIdx.x;
    int i = blockIdx.x * SCAN_B + t;
    int v = (i < N_NODES) ? g_cnt[i] : 0;
    s[t] = v;
    if (t < 32) {                       // block offset = sum of bsum[0..bid)
        int sum = 0;
        for (int b = t; b < blockIdx.x; b += 32) sum += g_bsum[b];
        #pragma unroll
        for (int o = 16; o > 0; o >>= 1)
            sum += __shfl_down_sync(0xFFFFFFFFu, sum, o);
        if (t == 0) sOff = sum;
    }
    __syncthreads();
    #pragma unroll
    for (int off = 1; off < SCAN_B; off <<= 1) {
        int a = (t >= off) ? s[t - off] : 0;
        __syncthreads();
        s[t] += a;
        __syncthreads();
    }
    if (i < N_NODES) {
        int excl = s[t] - v + sOff;
        g_rowptr[i] = excl;
        g_cursor[i] = excl;
    }
}

// ---------------------------------------------------------------------------
// (5) bucket scatter, 8 edges/thread (MLP)
// ---------------------------------------------------------------------------
__global__ void k_bucket(const int* __restrict__ ei) {
    int t = blockIdx.x * blockDim.x + threadIdx.x;
    if (t < N_EDGES / 8) {
        int4 r0 = ((const int4*)ei)[2 * t];
        int4 r1 = ((const int4*)ei)[2 * t + 1];
        int4 c0 = ((const int4*)(ei + N_EDGES))[2 * t];
        int4 c1 = ((const int4*)(ei + N_EDGES))[2 * t + 1];
        int p0 = atomicAdd(&g_cursor[c0.x], 1);
        int p1 = atomicAdd(&g_cursor[c0.y], 1);
        int p2 = atomicAdd(&g_cursor[c0.z], 1);
        int p3 = atomicAdd(&g_cursor[c0.w], 1);
        int p4 = atomicAdd(&g_cursor[c1.x], 1);
        int p5 = atomicAdd(&g_cursor[c1.y], 1);
        int p6 = atomicAdd(&g_cursor[c1.z], 1);
        int p7 = atomicAdd(&g_cursor[c1.w], 1);
        g_esrc[p0] = r0.x;
        g_esrc[p1] = r0.y;
        g_esrc[p2] = r0.z;
        g_esrc[p3] = r0.w;
        g_esrc[p4] = r1.x;
        g_esrc[p5] = r1.y;
        g_esrc[p6] = r1.z;
        g_esrc[p7] = r1.w;
    }
}

// ---------------------------------------------------------------------------
// (6) Aggregation layer 1 (warp per node, pure adds, 8-way MLP):
//   B1[i] = relu( dinv[i] * (H1[i] + sum_{e: col=i} H1[src]) + b1 )
// ---------------------------------------------------------------------------
__global__ void k_agg1(const float* __restrict__ b1) {
    int gtid = blockIdx.x * blockDim.x + threadIdx.x;
    int w = gtid >> 5, lane = gtid & 31;
    if (w >= N_NODES) return;
    const __half2* __restrict__ H = (const __half2*)g_H1h;   // row = 32 half2
    float2 acc = __half22float2(H[(size_t)w * 32 + lane]);   // self loop
    int beg = g_rowptr[w], end = beg + g_cnt[w];
    for (int base = beg; base < end; base += 32) {
        int nn = min(32, end - base);
        int s = (lane < nn) ? g_esrc[base + lane] : 0;
        int t = 0;
        for (; t + 8 <= nn; t += 8) {
            int s0 = __shfl_sync(0xFFFFFFFFu, s, t);
            int s1 = __shfl_sync(0xFFFFFFFFu, s, t + 1);
            int s2 = __shfl_sync(0xFFFFFFFFu, s, t + 2);
            int s3 = __shfl_sync(0xFFFFFFFFu, s, t + 3);
            int s4 = __shfl_sync(0xFFFFFFFFu, s, t + 4);
            int s5 = __shfl_sync(0xFFFFFFFFu, s, t + 5);
            int s6 = __shfl_sync(0xFFFFFFFFu, s, t + 6);
            int s7 = __shfl_sync(0xFFFFFFFFu, s, t + 7);
            float2 v0 = __half22float2(H[(size_t)s0 * 32 + lane]);
            float2 v1 = __half22float2(H[(size_t)s1 * 32 + lane]);
            float2 v2 = __half22float2(H[(size_t)s2 * 32 + lane]);
            float2 v3 = __half22float2(H[(size_t)s3 * 32 + lane]);
            float2 v4 = __half22float2(H[(size_t)s4 * 32 + lane]);
            float2 v5 = __half22float2(H[(size_t)s5 * 32 + lane]);
            float2 v6 = __half22float2(H[(size_t)s6 * 32 + lane]);
            float2 v7 = __half22float2(H[(size_t)s7 * 32 + lane]);
            acc.x += ((v0.x + v1.x) + (v2.x + v3.x))
                   + ((v4.x + v5.x) + (v6.x + v7.x));
            acc.y += ((v0.y + v1.y) + (v2.y + v3.y))
                   + ((v4.y + v5.y) + (v6.y + v7.y));
        }
        for (; t < nn; t++) {
            int sj = __shfl_sync(0xFFFFFFFFu, s, t);
            float2 v = __half22float2(H[(size_t)sj * 32 + lane]);
            acc.x += v.x; acc.y += v.y;
        }
    }
    float di = g_dinv[w];
    float2 b = ((const float2*)b1)[lane];
    float2 o;
    o.x = fmaxf(fmaf(acc.x, di, b.x), 0.0f);
    o.y = fmaxf(fmaf(acc.y, di, b.y), 0.0f);
    ((float2*)g_B1)[(size_t)w * 32 + lane] = o;
}

// ---------------------------------------------------------------------------
// (7) GEMM2: H2h[r] = half( (B1[r] @ W2) * dinv[r] ).  cols 0..39 active.
// ---------------------------------------------------------------------------
__global__ void k_gemm2(const float* __restrict__ W) {
    __shared__ float4 Ws4[16][40];   // 10 KB
    __shared__ float4 Xs4[32][16];   // 8 KB
    int tid = threadIdx.x;
    for (int idx = tid; idx < 16 * 40; idx += 256) {
        int kk = idx / 40, c = idx % 40, k0 = kk * 4;
        Ws4[kk][c] = make_float4(W[(k0 + 0) * 40 + c], W[(k0 + 1) * 40 + c],
                                 W[(k0 + 2) * 40 + c], W[(k0 + 3) * 40 + c]);
    }
    int row0 = blockIdx.x * 32;
    float* Xf = (float*)Xs4;
    for (int idx = tid; idx < 32 * 64; idx += 256)
        Xf[idx] = g_B1[(size_t)row0 * 64 + idx];
    __syncthreads();

    int tx = tid & 63, ty = tid >> 6;
    if (tx >= D_OUT) return;
    float acc[8] = {0, 0, 0, 0, 0, 0, 0, 0};
    #pragma unroll
    for (int kk = 0; kk < 16; kk++) {
        float4 w = Ws4[kk][tx];
        #pragma unroll
        for (int j = 0; j < 8; j++) {
            float4 xv = Xs4[ty * 8 + j][kk];
            acc[j] = fmaf(xv.x, w.x, fmaf(xv.y, w.y,
                     fmaf(xv.z, w.z, fmaf(xv.w, w.w, acc[j]))));
        }
    }
    #pragma unroll
    for (int j = 0; j < 8; j++) {
        int r = row0 + ty * 8 + j;
        g_H2h[(size_t)r * D_OUT + tx] = __float2half_rn(acc[j] * g_dinv[r]);
    }
}

// ---------------------------------------------------------------------------
// (8) Aggregation layer 2 + bias + log-softmax fused (warp per node, 8-way MLP)
// ---------------------------------------------------------------------------
__global__ void k_agg2(const float* __restrict__ b2, float* __restrict__ out) {
    int gtid = blockIdx.x * blockDim.x + threadIdx.x;
    int w = gtid >> 5, lane = gtid & 31;
    if (w >= N_NODES) return;
    const __half2* __restrict__ H = (const __half2*)g_H2h;  // row stride = 20 half2
    bool act = (lane < 20);
    float2 acc = make_float2(0.0f, 0.0f);
    if (act) acc = __half22float2(H[(size_t)w * 20 + lane]);
    int beg = g_rowptr[w], end = beg + g_cnt[w];
    for (int base = beg; base < end; base += 32) {
        int nn = min(32, end - base);
        int s = (lane < nn) ? g_esrc[base + lane] : 0;
        int t = 0;
        for (; t + 8 <= nn; t += 8) {
            int s0 = __shfl_sync(0xFFFFFFFFu, s, t);
            int s1 = __shfl_sync(0xFFFFFFFFu, s, t + 1);
            int s2 = __shfl_sync(0xFFFFFFFFu, s, t + 2);
            int s3 = __shfl_sync(0xFFFFFFFFu, s, t + 3);
            int s4 = __shfl_sync(0xFFFFFFFFu, s, t + 4);
            int s5 = __shfl_sync(0xFFFFFFFFu, s, t + 5);
            int s6 = __shfl_sync(0xFFFFFFFFu, s, t + 6);
            int s7 = __shfl_sync(0xFFFFFFFFu, s, t + 7);
            if (act) {
                float2 v0 = __half22float2(H[(size_t)s0 * 20 + lane]);
                float2 v1 = __half22float2(H[(size_t)s1 * 20 + lane]);
                float2 v2 = __half22float2(H[(size_t)s2 * 20 + lane]);
                float2 v3 = __half22float2(H[(size_t)s3 * 20 + lane]);
                float2 v4 = __half22float2(H[(size_t)s4 * 20 + lane]);
                float2 v5 = __half22float2(H[(size_t)s5 * 20 + lane]);
                float2 v6 = __half22float2(H[(size_t)s6 * 20 + lane]);
                float2 v7 = __half22float2(H[(size_t)s7 * 20 + lane]);
                acc.x += ((v0.x + v1.x) + (v2.x + v3.x))
                       + ((v4.x + v5.x) + (v6.x + v7.x));
                acc.y += ((v0.y + v1.y) + (v2.y + v3.y))
                       + ((v4.y + v5.y) + (v6.y + v7.y));
            }
        }
        for (; t < nn; t++) {
            int sj = __shfl_sync(0xFFFFFFFFu, s, t);
            if (act) {
                float2 v = __half22float2(H[(size_t)sj * 20 + lane]);
                acc.x += v.x; acc.y += v.y;
            }
        }
    }
    float di = g_dinv[w];
    float2 l = make_float2(-CUDART_INF_F, -CUDART_INF_F);
    if (act) {
        float2 b = ((const float2*)b2)[lane];
        l.x = fmaf(acc.x, di, b.x);
        l.y = fmaf(acc.y, di, b.y);
    }
    float m = fmaxf(l.x, l.y);
    #pragma unroll
    for (int o = 16; o > 0; o >>= 1) m = fmaxf(m, __shfl_xor_sync(0xFFFFFFFFu, m, o));
    float e = act ? (expf(l.x - m) + expf(l.y - m)) : 0.0f;
    #pragma unroll
    for (int o = 16; o > 0; o >>= 1) e += __shfl_xor_sync(0xFFFFFFFFu, e, o);
    float ls = m + logf(e);
    if (act) {
        float2* po = (float2*)out + (size_t)w * 20 + lane;
        *po = make_float2(l.x - ls, l.y - ls);
    }
}

// ---------------------------------------------------------------------------
// Launch (9 kernels — gemm1 deliberately at launch index 3 for ncu capture)
// ---------------------------------------------------------------------------
extern "C" void kernel_launch(void* const* d_in, const int* in_sizes, int n_in,
                              void* d_out, int out_size) {
    const float* x  = (const float*)d_in[0];
    const int*   ei = (const int*)  d_in[1];
    const float* W1 = (const float*)d_in[2];
    const float* b1 = (const float*)d_in[3];
    const float* W2 = (const float*)d_in[4];
    const float* b2 = (const float*)d_in[5];
    float* out = (float*)d_out;

    const int T = 256;

    k_zero_cnt   <<<(N_NODES + T - 1) / T, T>>>();                 // 0
    k_hist       <<<(N_EDGES / 8 + T - 1) / T, T>>>(ei);           // 1
    k_scan_reduce<<<NB, SCAN_B>>>();                               // 2 (+dinv)
    k_gemm1      <<<N_NODES / 32, 256>>>(x, W1);                   // 3 (profiled)
    k_scan_final <<<NB, SCAN_B>>>();                               // 4
    k_bucket     <<<(N_EDGES / 8 + T - 1) / T, T>>>(ei);           // 5
    k_agg1       <<<(N_NODES * 32 + T - 1) / T, T>>>(b1);          // 6
    k_gemm2      <<<N_NODES / 32, 256>>>(W2);                      // 7
    k_agg2       <<<(N_NODES * 32 + T - 1) / T, T>>>(b2, out);     // 8
}

// round 14
// speedup vs baseline: 1.2538x; 1.2538x over previous
#include <cuda_runtime.h>
#include <cuda_bf16.h>
#include <cuda_fp16.h>
#include <math_constants.h>
#include <mma.h>

using namespace nvcuda;

#define N_NODES 100000
#define N_EDGES 1600000
#define D_IN  64
#define D_HID 64
#define D_OUT 40

#define SCAN_B 512
#define NB ((N_NODES + SCAN_B - 1) / SCAN_B)   // 196

#define GEMM1_BLOCKS (N_NODES / 32)              // 3125
#define HIST_BLOCKS  ((N_EDGES / 4 + 255) / 256) // 1563

// ---------------------------------------------------------------------------
// Scratch (device globals — no runtime allocation allowed)
// ---------------------------------------------------------------------------
__device__ int   g_cnt   [N_NODES];            // in-degree (excl. self loop)
__device__ int   g_rowptr[N_NODES];            // exclusive prefix of cnt
__device__ int   g_cursor[N_NODES];            // bucket fill cursor
__device__ int   g_bsum  [NB];                 // per-scan-block sums
__device__ int   g_esrc  [N_EDGES];            // edge sources sorted by col
__device__ float g_dinv  [N_NODES];
// fp16 storage for gather-heavy tensors (accumulation stays fp32)
__device__ __align__(16) __half g_H1h[(size_t)N_NODES * D_HID]; // x@W1 (UNscaled)
__device__ __align__(16) __half g_B1h[(size_t)N_NODES * D_HID]; // relu(layer-1 out)
__device__ __align__(16) __half g_H2h[(size_t)N_NODES * D_OUT]; // (B1@W2)*dinv[row]

// ---------------------------------------------------------------------------
// (0) zero degree counters
// ---------------------------------------------------------------------------
__global__ void k_zero_cnt() {
    int i = blockIdx.x * blockDim.x + threadIdx.x;
    if (i < N_NODES) g_cnt[i] = 0;
}

// ---------------------------------------------------------------------------
// (1) FUSED: wmma gemm1 (blocks [0, GEMM1_BLOCKS)) + degree histogram (rest).
// gemm1: H1h[r] = half( x[r] @ W1 )   (UNscaled — dinv applied in agg1)
// ---------------------------------------------------------------------------
__global__ void k_gemm1_hist(const float* __restrict__ x,
                             const float* __restrict__ W,
                             const int* __restrict__ ei) {
    if (blockIdx.x >= GEMM1_BLOCKS) {          // ---- histogram part ----
        int t = (blockIdx.x - GEMM1_BLOCKS) * blockDim.x + threadIdx.x;
        if (t < N_EDGES / 4) {
            int4 c = ((const int4*)(ei + N_EDGES))[t];
            atomicAdd(&g_cnt[c.x], 1);
            atomicAdd(&g_cnt[c.y], 1);
            atomicAdd(&g_cnt[c.z], 1);
            atomicAdd(&g_cnt[c.w], 1);
        }
        return;
    }
    // ---- tensor-core gemm1: 32 rows x 64 cols per block, 8 warps (2m x 4n) ----
    __shared__ __half Xs[32][72];    // x tile  (fp16), ld=72  (~4.6 KB)
    __shared__ __half Ws[64][72];    // W1      (fp16), ld=72  (~9.2 KB)
    __shared__ float  Os[32][64];    // fp32 accum staging      (8 KB)
    int tid = threadIdx.x;
    int row0 = blockIdx.x * 32;

    for (int idx = tid; idx < 32 * 64; idx += 256) {
        int r = idx >> 6, c = idx & 63;
        Xs[r][c] = __float2half_rn(x[(size_t)(row0 + r) * 64 + c]);
    }
    for (int idx = tid; idx < 64 * 64; idx += 256) {
        int r = idx >> 6, c = idx & 63;
        Ws[r][c] = __float2half_rn(W[idx]);
    }
    __syncthreads();

    int w = tid >> 5;
    int m = (w & 1) * 16;
    int n = (w >> 1) * 16;
    wmma::fragment<wmma::matrix_a, 16, 16, 16, __half, wmma::row_major> fa;
    wmma::fragment<wmma::matrix_b, 16, 16, 16, __half, wmma::row_major> fb;
    wmma::fragment<wmma::accumulator, 16, 16, 16, float> fc;
    wmma::fill_fragment(fc, 0.0f);
    #pragma unroll
    for (int k = 0; k < 4; k++) {
        wmma::load_matrix_sync(fa, &Xs[m][k * 16], 72);
        wmma::load_matrix_sync(fb, &Ws[k * 16][n], 72);
        wmma::mma_sync(fc, fa, fb, fc);
    }
    wmma::store_matrix_sync(&Os[m][n], fc, 64, wmma::mem_row_major);
    __syncthreads();

    for (int idx = tid; idx < 32 * 64; idx += 256) {
        int r = idx >> 6, c = idx & 63;
        g_H1h[(size_t)(row0 + r) * D_HID + c] = __float2half_rn(Os[r][c]);
    }
}

// ---------------------------------------------------------------------------
// (2) scan: per-block reduce, then (3) scan + offsets + dinv
// ---------------------------------------------------------------------------
__global__ void k_scan_reduce() {   // <<<NB, SCAN_B>>>
    __shared__ int ssum[SCAN_B / 32];
    int tid = threadIdx.x;
    int i = blockIdx.x * SCAN_B + tid;
    int v = (i < N_NODES) ? g_cnt[i] : 0;
    #pragma unroll
    for (int o = 16; o > 0; o >>= 1) v += __shfl_down_sync(0xFFFFFFFFu, v, o);
    if ((tid & 31) == 0) ssum[tid >> 5] = v;
    __syncthreads();
    if (tid < SCAN_B / 32) {
        v = ssum[tid];
        #pragma unroll
        for (int o = SCAN_B / 64; o > 0; o >>= 1)
            v += __shfl_down_sync(0xFFFFFFFFu, v, o);
        if (tid == 0) g_bsum[blockIdx.x] = v;
    }
}

__global__ void k_scan_final() {    // <<<NB, SCAN_B>>>
    __shared__ int s[SCAN_B];
    __shared__ int sOff;
    int t = threadIdx.x;
    int i = blockIdx.x * SCAN_B + t;
    int v = (i < N_NODES) ? g_cnt[i] : 0;
    s[t] = v;
    if (t < 32) {                       // block offset = sum of bsum[0..bid)
        int sum = 0;
        for (int b = t; b < blockIdx.x; b += 32) sum += g_bsum[b];
        #pragma unroll
        for (int o = 16; o > 0; o >>= 1)
            sum += __shfl_down_sync(0xFFFFFFFFu, sum, o);
        if (t == 0) sOff = sum;
    }
    __syncthreads();
    #pragma unroll
    for (int off = 1; off < SCAN_B; off <<= 1) {
        int a = (t >= off) ? s[t - off] : 0;
        __syncthreads();
        s[t] += a;
        __syncthreads();
    }
    if (i < N_NODES) {
        int excl = s[t] - v + sOff;
        g_rowptr[i] = excl;
        g_cursor[i] = excl;
        g_dinv[i]   = rsqrtf((float)(v + 1));   // +1 self loop
    }
}

// ---------------------------------------------------------------------------
// (4) bucket scatter, 4 edges/thread (ILP)
// ---------------------------------------------------------------------------
__global__ void k_bucket(const int* __restrict__ ei) {
    int t = blockIdx.x * blockDim.x + threadIdx.x;
    if (t < N_EDGES / 4) {
        int4 r = ((const int4*)ei)[t];
        int4 c = ((const int4*)(ei + N_EDGES))[t];
        int p0 = atomicAdd(&g_cursor[c.x], 1);
        int p1 = atomicAdd(&g_cursor[c.y], 1);
        int p2 = atomicAdd(&g_cursor[c.z], 1);
        int p3 = atomicAdd(&g_cursor[c.w], 1);
        g_esrc[p0] = r.x;
        g_esrc[p1] = r.y;
        g_esrc[p2] = r.z;
        g_esrc[p3] = r.w;
    }
}

// ---------------------------------------------------------------------------
// (5) Aggregation layer 1 (warp per node, 8-way MLP, dinv[src] via shuffle):
//   B1h[i] = half(relu( dinv[i]*(H1[i]*dinv[i] + sum H1[s]*dinv[s]) + b1 ))
// ---------------------------------------------------------------------------
__global__ void k_agg1(const float* __restrict__ b1) {
    int gtid = blockIdx.x * blockDim.x + threadIdx.x;
    int w = gtid >> 5, lane = gtid & 31;
    if (w >= N_NODES) return;
    const __half2* __restrict__ H = (const __half2*)g_H1h;   // row = 32 half2
    float di = g_dinv[w];
    float2 self = __half22float2(H[(size_t)w * 32 + lane]);
    float2 acc;
    acc.x = self.x * di;
    acc.y = self.y * di;
    int beg = g_rowptr[w], end = beg + g_cnt[w];
    for (int base = beg; base < end; base += 32) {
        int nn = min(32, end - base);
        int s = 0; float d = 0.0f;
        if (lane < nn) { s = g_esrc[base + lane]; d = g_dinv[s]; }
        int t = 0;
        for (; t + 8 <= nn; t += 8) {
            int s0 = __shfl_sync(0xFFFFFFFFu, s, t);
            int s1 = __shfl_sync(0xFFFFFFFFu, s, t + 1);
            int s2 = __shfl_sync(0xFFFFFFFFu, s, t + 2);
            int s3 = __shfl_sync(0xFFFFFFFFu, s, t + 3);
            int s4 = __shfl_sync(0xFFFFFFFFu, s, t + 4);
            int s5 = __shfl_sync(0xFFFFFFFFu, s, t + 5);
            int s6 = __shfl_sync(0xFFFFFFFFu, s, t + 6);
            int s7 = __shfl_sync(0xFFFFFFFFu, s, t + 7);
            float d0 = __shfl_sync(0xFFFFFFFFu, d, t);
            float d1 = __shfl_sync(0xFFFFFFFFu, d, t + 1);
            float d2 = __shfl_sync(0xFFFFFFFFu, d, t + 2);
            float d3 = __shfl_sync(0xFFFFFFFFu, d, t + 3);
            float d4 = __shfl_sync(0xFFFFFFFFu, d, t + 4);
            float d5 = __shfl_sync(0xFFFFFFFFu, d, t + 5);
            float d6 = __shfl_sync(0xFFFFFFFFu, d, t + 6);
            float d7 = __shfl_sync(0xFFFFFFFFu, d, t + 7);
            float2 v0 = __half22float2(H[(size_t)s0 * 32 + lane]);
            float2 v1 = __half22float2(H[(size_t)s1 * 32 + lane]);
            float2 v2 = __half22float2(H[(size_t)s2 * 32 + lane]);
            float2 v3 = __half22float2(H[(size_t)s3 * 32 + lane]);
            float2 v4 = __half22float2(H[(size_t)s4 * 32 + lane]);
            float2 v5 = __half22float2(H[(size_t)s5 * 32 + lane]);
            float2 v6 = __half22float2(H[(size_t)s6 * 32 + lane]);
            float2 v7 = __half22float2(H[(size_t)s7 * 32 + lane]);
            acc.x = fmaf(v0.x, d0, acc.x); acc.y = fmaf(v0.y, d0, acc.y);
            acc.x = fmaf(v1.x, d1, acc.x); acc.y = fmaf(v1.y, d1, acc.y);
            acc.x = fmaf(v2.x, d2, acc.x); acc.y = fmaf(v2.y, d2, acc.y);
            acc.x = fmaf(v3.x, d3, acc.x); acc.y = fmaf(v3.y, d3, acc.y);
            acc.x = fmaf(v4.x, d4, acc.x); acc.y = fmaf(v4.y, d4, acc.y);
            acc.x = fmaf(v5.x, d5, acc.x); acc.y = fmaf(v5.y, d5, acc.y);
            acc.x = fmaf(v6.x, d6, acc.x); acc.y = fmaf(v6.y, d6, acc.y);
            acc.x = fmaf(v7.x, d7, acc.x); acc.y = fmaf(v7.y, d7, acc.y);
        }
        for (; t < nn; t++) {
            int sj = __shfl_sync(0xFFFFFFFFu, s, t);
            float dj = __shfl_sync(0xFFFFFFFFu, d, t);
            float2 v = __half22float2(H[(size_t)sj * 32 + lane]);
            acc.x = fmaf(v.x, dj, acc.x);
            acc.y = fmaf(v.y, dj, acc.y);
        }
    }
    float2 b = ((const float2*)b1)[lane];
    float2 o;
    o.x = fmaxf(fmaf(acc.x, di, b.x), 0.0f);
    o.y = fmaxf(fmaf(acc.y, di, b.y), 0.0f);
    ((__half2*)g_B1h)[(size_t)w * 32 + lane] = __float22half2_rn(o);
}

// ---------------------------------------------------------------------------
// (6) wmma GEMM2: H2h[r] = half( (B1[r] @ W2) * dinv[r] ).
//     32 rows x 48 cols (40 active), 6 active warps (2m x 3n).
// ---------------------------------------------------------------------------
__global__ void k_gemm2(const float* __restrict__ W) {
    __shared__ __half Xs[32][72];    // B1 tile (fp16), ld=72
    __shared__ __half Ws[64][56];    // W2 padded 64x48 (fp16), ld=56
    __shared__ float  Os[32][48];    // fp32 accum staging
    int tid = threadIdx.x;
    int row0 = blockIdx.x * 32;

    for (int idx = tid; idx < 64 * 56; idx += 256)
        ((__half*)Ws)[idx] = __float2half_rn(0.0f);
    __syncthreads();
    for (int idx = tid; idx < 64 * 40; idx += 256) {
        int r = idx / 40, c = idx % 40;
        Ws[r][c] = __float2half_rn(W[idx]);
    }
    for (int idx = tid; idx < 32 * 64; idx += 256) {
        int r = idx >> 6, c = idx & 63;
        Xs[r][c] = g_B1h[(size_t)(row0 + r) * 64 + c];
    }
    __syncthreads();

    int w = tid >> 5;
    if (w < 6) {
        int m = (w & 1) * 16;
        int n = (w >> 1) * 16;
        wmma::fragment<wmma::matrix_a, 16, 16, 16, __half, wmma::row_major> fa;
        wmma::fragment<wmma::matrix_b, 16, 16, 16, __half, wmma::row_major> fb;
        wmma::fragment<wmma::accumulator, 16, 16, 16, float> fc;
        wmma::fill_fragment(fc, 0.0f);
        #pragma unroll
        for (int k = 0; k < 4; k++) {
            wmma::load_matrix_sync(fa, &Xs[m][k * 16], 72);
            wmma::load_matrix_sync(fb, &Ws[k * 16][n], 56);
            wmma::mma_sync(fc, fa, fb, fc);
        }
        wmma::store_matrix_sync(&Os[m][n], fc, 48, wmma::mem_row_major);
    }
    __syncthreads();

    for (int idx = tid; idx < 32 * 40; idx += 256) {
        int r = idx / 40, c = idx % 40;
        int gr = row0 + r;
        g_H2h[(size_t)gr * D_OUT + c] = __float2half_rn(Os[r][c] * g_dinv[gr]);
    }
}

// ---------------------------------------------------------------------------
// (7) Aggregation layer 2 + bias + log-softmax fused (warp per node, 8-way MLP)
// ---------------------------------------------------------------------------
__global__ void k_agg2(const float* __restrict__ b2, float* __restrict__ out) {
    int gtid = blockIdx.x * blockDim.x + threadIdx.x;
    int w = gtid >> 5, lane = gtid & 31;
    if (w >= N_NODES) return;
    const __half2* __restrict__ H = (const __half2*)g_H2h;  // row stride = 20 half2
    bool act = (lane < 20);
    float2 acc = make_float2(0.0f, 0.0f);
    if (act) acc = __half22float2(H[(size_t)w * 20 + lane]);
    int beg = g_rowptr[w], end = beg + g_cnt[w];
    for (int base = beg; base < end; base += 32) {
        int nn = min(32, end - base);
        int s = (lane < nn) ? g_esrc[base + lane] : 0;
        int t = 0;
        for (; t + 8 <= nn; t += 8) {
            int s0 = __shfl_sync(0xFFFFFFFFu, s, t);
            int s1 = __shfl_sync(0xFFFFFFFFu, s, t + 1);
            int s2 = __shfl_sync(0xFFFFFFFFu, s, t + 2);
            int s3 = __shfl_sync(0xFFFFFFFFu, s, t + 3);
            int s4 = __shfl_sync(0xFFFFFFFFu, s, t + 4);
            int s5 = __shfl_sync(0xFFFFFFFFu, s, t + 5);
            int s6 = __shfl_sync(0xFFFFFFFFu, s, t + 6);
            int s7 = __shfl_sync(0xFFFFFFFFu, s, t + 7);
            if (act) {
                float2 v0 = __half22float2(H[(size_t)s0 * 20 + lane]);
                float2 v1 = __half22float2(H[(size_t)s1 * 20 + lane]);
                float2 v2 = __half22float2(H[(size_t)s2 * 20 + lane]);
                float2 v3 = __half22float2(H[(size_t)s3 * 20 + lane]);
                float2 v4 = __half22float2(H[(size_t)s4 * 20 + lane]);
                float2 v5 = __half22float2(H[(size_t)s5 * 20 + lane]);
                float2 v6 = __half22float2(H[(size_t)s6 * 20 + lane]);
                float2 v7 = __half22float2(H[(size_t)s7 * 20 + lane]);
                acc.x += ((v0.x + v1.x) + (v2.x + v3.x))
                       + ((v4.x + v5.x) + (v6.x + v7.x));
                acc.y += ((v0.y + v1.y) + (v2.y + v3.y))
                       + ((v4.y + v5.y) + (v6.y + v7.y));
            }
        }
        for (; t < nn; t++) {
            int sj = __shfl_sync(0xFFFFFFFFu, s, t);
            if (act) {
                float2 v = __half22float2(H[(size_t)sj * 20 + lane]);
                acc.x += v.x; acc.y += v.y;
            }
        }
    }
    float di = g_dinv[w];
    float2 l = make_float2(-CUDART_INF_F, -CUDART_INF_F);
    if (act) {
        float2 b = ((const float2*)b2)[lane];
        l.x = fmaf(acc.x, di, b.x);
        l.y = fmaf(acc.y, di, b.y);
    }
    float m = fmaxf(l.x, l.y);
    #pragma unroll
    for (int o = 16; o > 0; o >>= 1) m = fmaxf(m, __shfl_xor_sync(0xFFFFFFFFu, m, o));
    float e = act ? (expf(l.x - m) + expf(l.y - m)) : 0.0f;
    #pragma unroll
    for (int o = 16; o > 0; o >>= 1) e += __shfl_xor_sync(0xFFFFFFFFu, e, o);
    float ls = m + logf(e);
    if (act) {
        float2* po = (float2*)out + (size_t)w * 20 + lane;
        *po = make_float2(l.x - ls, l.y - ls);
    }
}

// ---------------------------------------------------------------------------
// Launch (8 kernels)
// ---------------------------------------------------------------------------
extern "C" void kernel_launch(void* const* d_in, const int* in_sizes, int n_in,
                              void* d_out, int out_size) {
    const float* x  = (const float*)d_in[0];
    const int*   ei = (const int*)  d_in[1];
    const float* W1 = (const float*)d_in[2];
    const float* b1 = (const float*)d_in[3];
    const float* W2 = (const float*)d_in[4];
    const float* b2 = (const float*)d_in[5];
    float* out = (float*)d_out;

    const int T = 256;

    k_zero_cnt  <<<(N_NODES + T - 1) / T, T>>>();
    k_gemm1_hist<<<GEMM1_BLOCKS + HIST_BLOCKS, 256>>>(x, W1, ei);  // fused
    k_scan_reduce<<<NB, SCAN_B>>>();
    k_scan_final <<<NB, SCAN_B>>>();
    k_bucket     <<<(N_EDGES / 4 + T - 1) / T, T>>>(ei);

    k_agg1 <<<(N_NODES * 32 + T - 1) / T, T>>>(b1);

    k_gemm2<<<N_NODES / 32, 256>>>(W2);
    k_agg2 <<<(N_NODES * 32 + T - 1) / T, T>>>(b2, out);
}